// round 15
// baseline (speedup 1.0000x reference)
#include <cuda_runtime.h>
#include <math.h>

// ---------------------------------------------------------------------------
// Problem constants
// ---------------------------------------------------------------------------
namespace {
constexpr int Bc = 64, Tc = 32, TMAX = 31;
constexpr int Fc = 512, Lc = 196, Ec = 512, Hc = 512, Ac = 512, Vc = 10000;
constexpr int NCAT = 3072;            // de(512) | fbeta(512) | hh gates(2048)
constexpr long long PRED_SZ = (long long)Bc * TMAX * Vc;   // 19,840,000
constexpr int NCTA = 296;             // persistent grid: 2 CTAs per SM
constexpr int NGRP = 8;               // barrier tree groups (296 = 8 * 37)
constexpr unsigned GRP_SZ = 37u;
}

// ---------------------------------------------------------------------------
// Static scratch (no allocations allowed)
// ---------------------------------------------------------------------------
__device__ float g_en_att[Bc * Lc * Ac];          // [B*L, A]
__device__ float g_meanf[Bc * Fc];
__device__ float g_hc[Bc * 1024];                 // h = cols[0:512), c = cols[512:1024)
__device__ float g_hp[4 * Bc * NCAT];             // hproj partials (4 k-split planes)
__device__ float g_scp[2 * Bc * 200];             // partial attention scores (a-halves)
__device__ float g_xz[Bc * Fc];                   // gated context z
__device__ float g_Wcat[NCAT * Hc];               // [W_dec ; W_fbeta ; W_hh]
__device__ float g_bcat[NCAT];
__device__ float g_Winit[1024 * Fc];              // [W_init_h ; W_init_c]
__device__ float g_binit[1024];
__device__ float g_xemb[TMAX * Bc * Ec];          // gathered embeddings (tf32-rounded)
__device__ float g_embg[TMAX * Bc * 2048];        // emb @ W_ih_emb^T
__device__ float g_hnew_all[TMAX * Bc * Hc];      // unmasked h_new (tf32-rounded)

// two-level barrier tree: 8 group counters (128B apart) + root
__device__ unsigned g_bar1[NGRP * 32];
__device__ unsigned g_bar2;

// tf32-prerounded GEMM operands (bit patterns of rna-rounded fp32)
__device__ unsigned g_Wenc_t[Ac * Fc];            // W_enc
__device__ unsigned g_Wihe_t[2048 * Ec];          // W_ih[:, 0:512] dense
__device__ unsigned g_Wout_t[Vc * Hc];            // W_out
__device__ unsigned g_feat_t[Bc * Lc * Fc];       // features (as [B*L, F])

__device__ __forceinline__ float tanh_fast(float x) {
    float y;
    asm("tanh.approx.f32 %0, %1;" : "=f"(y) : "f"(x));
    return y;
}
__device__ __forceinline__ float sigmoid_fast(float x) {
    return 1.0f / (1.0f + __expf(-x));
}
__device__ __forceinline__ unsigned f2tf32(float x) {
    unsigned r;
    asm("cvt.rna.tf32.f32 %0, %1;" : "=r"(r) : "f"(x));
    return r;
}

// ---------------------------------------------------------------------------
// Launch 1: weight packing + tf32 pre-rounding + barrier reset
// ---------------------------------------------------------------------------
__global__ void prep_weights(const float* __restrict__ Wdec,
                             const float* __restrict__ Wfb,
                             const float* __restrict__ Whh,
                             const float* __restrict__ bdec,
                             const float* __restrict__ bfb,
                             const float* __restrict__ bih,
                             const float* __restrict__ bhh,
                             const float* __restrict__ Wih_,
                             const float* __restrict__ Wic_,
                             const float* __restrict__ bih0,
                             const float* __restrict__ bic0,
                             const float* __restrict__ Wenc,
                             const float* __restrict__ WihFull,
                             const float* __restrict__ Wout)
{
    int idx = blockIdx.x * 256 + threadIdx.x;
    if (idx == 0) g_bar2 = 0u;
    if (idx < NGRP * 32) g_bar1[idx] = 0u;
    if (idx < NCAT * Hc) {
        int n = idx / Hc, k = idx % Hc;
        float v;
        if (n < 512)       v = Wdec[n * Hc + k];
        else if (n < 1024) v = Wfb[(n - 512) * Hc + k];
        else               v = Whh[(n - 1024) * Hc + k];
        g_Wcat[idx] = v;
    }
    if (idx < NCAT) {
        float v;
        if (idx < 512)       v = bdec[idx];
        else if (idx < 1024) v = bfb[idx - 512];
        else                 v = bih[idx - 1024] + bhh[idx - 1024];
        g_bcat[idx] = v;
    }
    if (idx < 1024 * Fc) {
        int n = idx / Fc, k = idx % Fc;
        g_Winit[idx] = (n < 512) ? Wih_[n * Fc + k] : Wic_[(n - 512) * Fc + k];
    }
    if (idx < 1024)
        g_binit[idx] = (idx < 512) ? bih0[idx] : bic0[idx - 512];

    // tf32 pre-rounding
    if (idx < Ac * Fc)
        g_Wenc_t[idx] = f2tf32(Wenc[idx]);
    if (idx < 2048 * Ec) {
        int n = idx >> 9, k = idx & 511;
        g_Wihe_t[idx] = f2tf32(WihFull[(size_t)n * 1024 + k]);
    }
    if (idx < Vc * Hc)
        g_Wout_t[idx] = f2tf32(Wout[idx]);
}

// ---------------------------------------------------------------------------
// Launch 2: mean over L + embedding gather + features tf32 copy (merged)
// ---------------------------------------------------------------------------
__global__ void gather(const float* __restrict__ feat,
                       const float* __restrict__ Wemb,
                       const int* __restrict__ captions)
{
    if (blockIdx.x < 64) {
        int b = blockIdx.x, f = threadIdx.x;   // 512 threads
        const float* p = feat + (size_t)b * Fc * Lc + (size_t)f * Lc;
        float s = 0.f;
        #pragma unroll 4
        for (int l = 0; l < Lc; ++l) s += p[l];
        g_meanf[b * Fc + f] = s * (1.0f / (float)Lc);
    } else if (blockIdx.x < 2048) {
        int u = blockIdx.x - 64;
        int t = u >> 6, b = u & 63, e = threadIdx.x;
        int tok = captions[b * Tc + t];
        float w = Wemb[(size_t)tok * Ec + e];
        g_xemb[((size_t)t * Bc + b) * Ec + e] = __uint_as_float(f2tf32(w));
    } else {
        size_t i = (size_t)(blockIdx.x - 2048) * 512 + threadIdx.x;
        g_feat_t[i] = f2tf32(feat[i]);
    }
}

// ---------------------------------------------------------------------------
// Two-level grid barrier: group red -> leader red root -> all poll root.
// Same-address atomic serialization drops from 296 ops to max(37, 8) ops.
// Release/acquire chain: member release->group, leader acquire group +
// release->root, members acquire root (transitive happens-before).
// ---------------------------------------------------------------------------
__device__ __forceinline__ void gsync(unsigned& e)
{
    __syncthreads();
    if (threadIdx.x == 0) {
        const int grp = blockIdx.x & (NGRP - 1);
        unsigned* gc = &g_bar1[grp * 32];
        asm volatile("red.release.gpu.global.add.u32 [%0], %1;"
                     :: "l"(gc), "r"(1u) : "memory");
        e += 1;
        if (blockIdx.x < NGRP) {            // leader of group `bid`
            unsigned v;
            do {
                asm volatile("ld.acquire.gpu.global.u32 %0, [%1];"
                             : "=r"(v) : "l"(gc) : "memory");
            } while (v < GRP_SZ * e);
            asm volatile("red.release.gpu.global.add.u32 [%0], %1;"
                         :: "l"(&g_bar2), "r"(1u) : "memory");
        }
        unsigned v;
        do {
            asm volatile("ld.acquire.gpu.global.u32 %0, [%1];"
                         : "=r"(v) : "l"(&g_bar2) : "memory");
        } while (v < (unsigned)NGRP * e);
    }
    __syncthreads();
}

// ---------------------------------------------------------------------------
// 64x32 fp32 tile GEMM (double-buffered, BK=16, 256 threads, TM4 x TN2)
// ---------------------------------------------------------------------------
__device__ __forceinline__ void tile_gemm(
    const float* __restrict__ A, int ldA,
    const float* __restrict__ Brow, int ldB,
    int koff, int ktiles,
    const float* __restrict__ bias,
    float* __restrict__ dst, int ldC,
    float (&As)[2][16][64], float (&Bs)[2][16][32])
{
    const int tid = threadIdx.x;
    const int tx = tid & 15, ty = tid >> 4;
    const int arow = tid >> 2, acol = (tid & 3) * 4;
    const int brow = tid >> 3, bcol = (tid & 7) * 2;

    const float* aptr = A + (size_t)arow * ldA + koff + acol;
    const float* bptr = Brow + (size_t)brow * ldB + koff + bcol;

    float acc[4][2];
    #pragma unroll
    for (int i = 0; i < 4; ++i) { acc[i][0] = 0.f; acc[i][1] = 0.f; }

    float4 av = *reinterpret_cast<const float4*>(aptr);
    float2 bv = *reinterpret_cast<const float2*>(bptr);
    As[0][acol + 0][arow] = av.x; As[0][acol + 1][arow] = av.y;
    As[0][acol + 2][arow] = av.z; As[0][acol + 3][arow] = av.w;
    Bs[0][bcol + 0][brow] = bv.x; Bs[0][bcol + 1][brow] = bv.y;
    __syncthreads();

    for (int it = 0; it < ktiles; ++it) {
        const int cur = it & 1;
        if (it + 1 < ktiles) {
            av = *reinterpret_cast<const float4*>(aptr + (it + 1) * 16);
            bv = *reinterpret_cast<const float2*>(bptr + (it + 1) * 16);
        }
        #pragma unroll
        for (int k = 0; k < 16; ++k) {
            float4 a4 = *reinterpret_cast<const float4*>(&As[cur][k][ty * 4]);
            float2 b2 = *reinterpret_cast<const float2*>(&Bs[cur][k][tx * 2]);
            acc[0][0] += a4.x * b2.x; acc[0][1] += a4.x * b2.y;
            acc[1][0] += a4.y * b2.x; acc[1][1] += a4.y * b2.y;
            acc[2][0] += a4.z * b2.x; acc[2][1] += a4.z * b2.y;
            acc[3][0] += a4.w * b2.x; acc[3][1] += a4.w * b2.y;
        }
        if (it + 1 < ktiles) {
            const int nxt = cur ^ 1;
            As[nxt][acol + 0][arow] = av.x; As[nxt][acol + 1][arow] = av.y;
            As[nxt][acol + 2][arow] = av.z; As[nxt][acol + 3][arow] = av.w;
            Bs[nxt][bcol + 0][brow] = bv.x; Bs[nxt][bcol + 1][brow] = bv.y;
        }
        __syncthreads();
    }

    #pragma unroll
    for (int i = 0; i < 4; ++i) {
        float b0 = bias ? bias[tx * 2 + 0] : 0.f;
        float b1 = bias ? bias[tx * 2 + 1] : 0.f;
        float* d = dst + (size_t)(ty * 4 + i) * ldC + tx * 2;
        d[0] = acc[i][0] + b0;
        d[1] = acc[i][1] + b1;
    }
}

// ---------------------------------------------------------------------------
// Persistent step loop (phase structure = R12 best; barrier = tree)
// ---------------------------------------------------------------------------
__global__ __launch_bounds__(256, 2) void step_loop(
    const float* __restrict__ features,
    const float* __restrict__ W_ih,
    const float* __restrict__ Wfull,
    const int*   __restrict__ lengths,
    float* __restrict__ alpha_out)
{
    __shared__ float As[2][16][64];
    __shared__ float Bs[2][16][32];
    __shared__ float A4[2][16][17];
    __shared__ float B4[2][16][68];
    __shared__ float sg[16][68];
    __shared__ float s_de[256];
    __shared__ float s_wf[256];
    __shared__ float s_sc[200];
    __shared__ float s_red[256];

    const int bid = blockIdx.x;
    const int tid = threadIdx.x;
    unsigned epoch = 0;

    // ---- P0: h0/c0 = meanf @ Winit^T + binit (32 units, full K) -----------
    if (bid < 32) {
        const int n0 = bid * 32;
        tile_gemm(g_meanf, 512, g_Winit + (size_t)n0 * 512, 512, 0, 32,
                  g_binit + n0, g_hc + n0, 1024, As, Bs);
    }
    gsync(epoch);

    for (int t = 0; t < TMAX; ++t) {
        // ---- P1: de/fbeta partials: 32 tiles(32col) x split-4 -------------
        if (bid < 128) {
            const int s = bid >> 5, n0 = (bid & 31) * 32;
            tile_gemm(g_hc, 1024, g_Wcat + (size_t)n0 * 512, 512,
                      s * 128, 8, nullptr,
                      g_hp + (size_t)s * Bc * NCAT + n0, NCAT, As, Bs);
        }
        gsync(epoch);

        // ---- P2: partial scores (a-halves) || hh units 0..127 -------------
        if (bid >= 128 && bid < 256) {
            const int u = bid - 128;
            const int b = u & 63, ah = u >> 6;
            if ((lengths[b] - 1) > t) {
                {
                    const int a = ah * 256 + tid;
                    float d = g_bcat[a];
                    #pragma unroll
                    for (int s = 0; s < 4; ++s)
                        d += g_hp[((size_t)s * Bc + b) * NCAT + a];
                    s_de[tid] = d;
                    s_wf[tid] = Wfull[a];
                }
                __syncthreads();
                const int warp = tid >> 5, lane = tid & 31;
                for (int l = warp; l < Lc; l += 8) {
                    const float* ea = g_en_att + ((size_t)b * Lc + l) * Ac
                                               + ah * 256;
                    float s = 0.f;
                    #pragma unroll
                    for (int i = lane; i < 256; i += 32)
                        s += tanh_fast(ea[i] + s_de[i]) * s_wf[i];
                    #pragma unroll
                    for (int o = 16; o > 0; o >>= 1)
                        s += __shfl_xor_sync(0xffffffffu, s, o);
                    if (lane == 0)
                        g_scp[((size_t)ah * Bc + b) * 200 + l] = s;
                }
            }
        } else if (bid < 128) {
            const int s = bid >> 6, n0 = 1024 + (bid & 63) * 32;
            tile_gemm(g_hc, 1024, g_Wcat + (size_t)n0 * 512, 512,
                      s * 128, 8, nullptr,
                      g_hp + (size_t)s * Bc * NCAT + n0, NCAT, As, Bs);
        }
        gsync(epoch);

        // ---- P3: softmax + z (f-halves) || hh units 128..255 --------------
        if (bid >= 128 && bid < 256) {
            const int u = bid - 128;
            const int b = u & 63, fh = u >> 6;
            const bool active = (lengths[b] - 1) > t;
            if (!active) {
                if (fh == 0 && tid < Lc)
                    alpha_out[((size_t)b * TMAX + t) * Lc + tid] = 0.f;
            } else {
                float v = (tid < Lc)
                    ? g_scp[(size_t)b * 200 + tid] +
                      g_scp[((size_t)Bc + b) * 200 + tid]
                    : -3.4e38f;
                s_red[tid] = v; __syncthreads();
                for (int s = 128; s > 0; s >>= 1) {
                    if (tid < s) s_red[tid] = fmaxf(s_red[tid], s_red[tid + s]);
                    __syncthreads();
                }
                float mx = s_red[0]; __syncthreads();
                float e = (tid < Lc) ? __expf(v - mx) : 0.f;
                s_red[tid] = e; __syncthreads();
                for (int s = 128; s > 0; s >>= 1) {
                    if (tid < s) s_red[tid] += s_red[tid + s];
                    __syncthreads();
                }
                float inv = 1.f / s_red[0];
                if (tid < Lc) {
                    float a = e * inv;
                    s_sc[tid] = a;
                    if (fh == 0)
                        alpha_out[((size_t)b * TMAX + t) * Lc + tid] = a;
                }
                __syncthreads();

                const int f = fh * 256 + tid;
                float fb = g_bcat[512 + f];
                #pragma unroll
                for (int s = 0; s < 4; ++s)
                    fb += g_hp[((size_t)s * Bc + b) * NCAT + 512 + f];
                const float* fp = features + (size_t)b * Lc * Fc + f;
                float acc = 0.f;
                #pragma unroll 4
                for (int l = 0; l < Lc; ++l)
                    acc += fp[(size_t)l * Fc] * s_sc[l];
                g_xz[b * Fc + f] = acc * sigmoid_fast(fb);
            }
        } else if (bid < 128) {
            const int s = 2 + (bid >> 6), n0 = 1024 + (bid & 63) * 32;
            tile_gemm(g_hc, 1024, g_Wcat + (size_t)n0 * 512, 512,
                      s * 128, 8, nullptr,
                      g_hp + (size_t)s * Bc * NCAT + n0, NCAT, As, Bs);
        }
        gsync(epoch);

        // ---- P4: gate-grouped z-GEMM (16x64 tile, full K) + fused LSTM ----
        if (bid < 128) {
            const int bt = bid >> 5, ng = bid & 31;
            const int b0 = bt * 16;
            const int tx = tid & 15, ty = tid >> 4;

            const int ar = tid >> 2, ac = (tid & 3) * 4;
            const float* aptr = g_xz + (size_t)(b0 + (ar & 15)) * 512 + ac;
            const int br = tid >> 2, bc = (tid & 3) * 4;
            const int grow = (br >> 4) * 512 + ng * 16 + (br & 15);
            const float* bptr = W_ih + (size_t)grow * 1024 + 512 + bc;

            float acc0 = 0.f, acc1 = 0.f, acc2 = 0.f, acc3 = 0.f;
            float4 av, bv;
            if (tid < 64) av = *reinterpret_cast<const float4*>(aptr);
            bv = *reinterpret_cast<const float4*>(bptr);
            if (tid < 64) {
                A4[0][ac + 0][ar] = av.x; A4[0][ac + 1][ar] = av.y;
                A4[0][ac + 2][ar] = av.z; A4[0][ac + 3][ar] = av.w;
            }
            B4[0][bc + 0][br] = bv.x; B4[0][bc + 1][br] = bv.y;
            B4[0][bc + 2][br] = bv.z; B4[0][bc + 3][br] = bv.w;
            __syncthreads();

            for (int it2 = 0; it2 < 32; ++it2) {
                const int cur = it2 & 1;
                if (it2 + 1 < 32) {
                    if (tid < 64)
                        av = *reinterpret_cast<const float4*>(aptr + (it2 + 1) * 16);
                    bv = *reinterpret_cast<const float4*>(bptr + (it2 + 1) * 16);
                }
                #pragma unroll
                for (int k = 0; k < 16; ++k) {
                    float a = A4[cur][k][ty];
                    float4 b4 = *reinterpret_cast<const float4*>(&B4[cur][k][tx * 4]);
                    acc0 += a * b4.x; acc1 += a * b4.y;
                    acc2 += a * b4.z; acc3 += a * b4.w;
                }
                if (it2 + 1 < 32) {
                    const int nxt = cur ^ 1;
                    if (tid < 64) {
                        A4[nxt][ac + 0][ar] = av.x; A4[nxt][ac + 1][ar] = av.y;
                        A4[nxt][ac + 2][ar] = av.z; A4[nxt][ac + 3][ar] = av.w;
                    }
                    B4[nxt][bc + 0][br] = bv.x; B4[nxt][bc + 1][br] = bv.y;
                    B4[nxt][bc + 2][br] = bv.z; B4[nxt][bc + 3][br] = bv.w;
                }
                __syncthreads();
            }

            sg[ty][tx * 4 + 0] = acc0; sg[ty][tx * 4 + 1] = acc1;
            sg[ty][tx * 4 + 2] = acc2; sg[ty][tx * 4 + 3] = acc3;
            __syncthreads();

            {
                const int bl = tid >> 4, nl = tid & 15;
                const int b = b0 + bl, n = ng * 16 + nl;
                const bool active = (lengths[b] - 1) > t;
                float gate[4];
                #pragma unroll
                for (int g = 0; g < 4; ++g) {
                    const int col = g * 512 + n;
                    float v = sg[bl][g * 16 + nl]
                            + g_bcat[1024 + col]
                            + g_embg[((size_t)t * Bc + b) * 2048 + col];
                    #pragma unroll
                    for (int s = 0; s < 4; ++s)
                        v += g_hp[((size_t)s * Bc + b) * NCAT + 1024 + col];
                    gate[g] = v;
                }
                float c  = g_hc[b * 1024 + 512 + n];
                float si = sigmoid_fast(gate[0]);
                float sf = sigmoid_fast(gate[1]);
                float so = sigmoid_fast(gate[3]);
                float cn = sf * c + si * tanhf(gate[2]);
                float hn = so * tanhf(cn);
                g_hnew_all[((size_t)t * Bc + b) * Hc + n] =
                    __uint_as_float(f2tf32(hn));
                if (active) {
                    g_hc[b * 1024 + n]       = hn;
                    g_hc[b * 1024 + 512 + n] = cn;
                }
            }
        }
        gsync(epoch);
    }
}

// ---------------------------------------------------------------------------
// tf32 tensor-core NT GEMM: cp.async pipeline, operands pre-rounded.
// ---------------------------------------------------------------------------
template<int MODE>
__global__ __launch_bounds__(256) void gemm_tc(
    int M, int N, int K,
    const unsigned* __restrict__ A,
    const unsigned* __restrict__ B, int ldB,
    const float* __restrict__ bias,
    float* __restrict__ C, int ldC,
    const int* __restrict__ lengths, float* __restrict__ predBase)
{
    constexpr int BM = 64, BN = 64, BK = 32, PAD = 4;
    __shared__ unsigned As[2][BM][BK + PAD];
    __shared__ unsigned Bs[2][BN][BK + PAD];

    const int tid = threadIdx.x;
    const int lane = tid & 31, wid = tid >> 5;
    const int wm = wid & 3, wn = wid >> 2;
    const int g = lane >> 2, tg = lane & 3;
    const int bm = blockIdx.y * BM, bn = blockIdx.x * BN;

    const int lr = tid >> 2;
    const int lc = (tid & 3) * 8;
    const unsigned* ap = A + (size_t)(bm + lr) * K + lc;
    const bool bval = (bn + lr) < N;
    const unsigned* bp = B + (bval ? (size_t)(bn + lr) * ldB : 0) + lc;
    const int bsz = bval ? 16 : 0;

    const unsigned sa = (unsigned)__cvta_generic_to_shared(&As[0][lr][lc]);
    const unsigned sb = (unsigned)__cvta_generic_to_shared(&Bs[0][lr][lc]);
    const unsigned bufstride = (unsigned)(sizeof(unsigned) * BM * (BK + PAD));

    float acc[4][4];
    #pragma unroll
    for (int i = 0; i < 4; ++i)
        #pragma unroll
        for (int j = 0; j < 4; ++j) acc[i][j] = 0.f;

    auto stage = [&](int buf, int it) {
        const unsigned* a = ap + it * BK;
        const unsigned* b = bp + it * BK;
        unsigned da = sa + buf * bufstride;
        unsigned db = sb + buf * bufstride;
        asm volatile("cp.async.ca.shared.global [%0], [%1], 16;"
                     :: "r"(da), "l"(a));
        asm volatile("cp.async.ca.shared.global [%0], [%1], 16;"
                     :: "r"(da + 16), "l"(a + 4));
        asm volatile("cp.async.ca.shared.global [%0], [%1], 16, %2;"
                     :: "r"(db), "l"(b), "r"(bsz));
        asm volatile("cp.async.ca.shared.global [%0], [%1], 16, %2;"
                     :: "r"(db + 16), "l"(b + 4), "r"(bsz));
        asm volatile("cp.async.commit_group;");
    };

    stage(0, 0);
    const int nt = K / BK;
    for (int it = 0; it < nt; ++it) {
        const int cur = it & 1;
        if (it + 1 < nt) {
            stage(cur ^ 1, it + 1);
            asm volatile("cp.async.wait_group 1;");
        } else {
            asm volatile("cp.async.wait_group 0;");
        }
        __syncthreads();

        #pragma unroll
        for (int ks = 0; ks < 4; ++ks) {
            const int k0 = ks * 8;
            unsigned fa0 = As[cur][wm * 16 + g][k0 + tg];
            unsigned fa1 = As[cur][wm * 16 + g + 8][k0 + tg];
            unsigned fa2 = As[cur][wm * 16 + g][k0 + tg + 4];
            unsigned fa3 = As[cur][wm * 16 + g + 8][k0 + tg + 4];
            #pragma unroll
            for (int t8 = 0; t8 < 4; ++t8) {
                unsigned fb0 = Bs[cur][wn * 32 + t8 * 8 + g][k0 + tg];
                unsigned fb1 = Bs[cur][wn * 32 + t8 * 8 + g][k0 + tg + 4];
                asm volatile(
                    "mma.sync.aligned.m16n8k8.row.col.f32.tf32.tf32.f32 "
                    "{%0,%1,%2,%3}, {%4,%5,%6,%7}, {%8,%9}, {%0,%1,%2,%3};"
                    : "+f"(acc[t8][0]), "+f"(acc[t8][1]),
                      "+f"(acc[t8][2]), "+f"(acc[t8][3])
                    : "r"(fa0), "r"(fa1), "r"(fa2), "r"(fa3),
                      "r"(fb0), "r"(fb1));
            }
        }
        __syncthreads();
    }

    #pragma unroll
    for (int t8 = 0; t8 < 4; ++t8) {
        const int col = bn + wn * 32 + t8 * 8 + 2 * tg;
        if (col >= N) continue;
        float bb0 = bias ? bias[col]     : 0.f;
        float bb1 = bias ? bias[col + 1] : 0.f;
        #pragma unroll
        for (int half = 0; half < 2; ++half) {
            const int m = bm + wm * 16 + g + half * 8;
            float v0 = acc[t8][half * 2 + 0] + bb0;
            float v1 = acc[t8][half * 2 + 1] + bb1;
            float* dst;
            if (MODE == 2) {
                const int b = m & 63, t = m >> 6;
                if (!((lengths[b] - 1) > t)) { v0 = 0.f; v1 = 0.f; }
                dst = predBase + ((size_t)b * TMAX + t) * Vc + col;
            } else {
                dst = C + (size_t)m * ldC + col;
            }
            *reinterpret_cast<float2*>(dst) = make_float2(v0, v1);
        }
    }
}

// ---------------------------------------------------------------------------
// Host driver: 6 launches total (graph-capturable)
// ---------------------------------------------------------------------------
extern "C" void kernel_launch(void* const* d_in, const int* in_sizes, int n_in,
                              void* d_out, int out_size)
{
    const float* features = (const float*)d_in[0];
    const int*   captions = (const int*)  d_in[1];
    const int*   lengths  = (const int*)  d_in[2];
    const float* W_emb    = (const float*)d_in[3];
    const float* W_enc    = (const float*)d_in[4];
    const float* b_enc    = (const float*)d_in[5];
    const float* W_dec    = (const float*)d_in[6];
    const float* b_dec    = (const float*)d_in[7];
    const float* W_full   = (const float*)d_in[8];
    /* d_in[9] = b_full: softmax shift-invariant, unused */
    const float* W_fbeta  = (const float*)d_in[10];
    const float* b_fbeta  = (const float*)d_in[11];
    const float* W_ih     = (const float*)d_in[12];
    const float* W_hh     = (const float*)d_in[13];
    const float* b_ih     = (const float*)d_in[14];
    const float* b_hh     = (const float*)d_in[15];
    const float* W_out    = (const float*)d_in[16];
    const float* b_out    = (const float*)d_in[17];
    const float* W_init_h = (const float*)d_in[18];
    const float* b_init_h = (const float*)d_in[19];
    const float* W_init_c = (const float*)d_in[20];
    const float* b_init_c = (const float*)d_in[21];

    float* out       = (float*)d_out;
    float* alpha_out = out + PRED_SZ;

    float *p_en_att, *p_xemb, *p_embg, *p_hnew_all;
    unsigned *p_Wenc_t, *p_Wihe_t, *p_Wout_t, *p_feat_t;
    cudaGetSymbolAddress((void**)&p_en_att,   g_en_att);
    cudaGetSymbolAddress((void**)&p_xemb,     g_xemb);
    cudaGetSymbolAddress((void**)&p_embg,     g_embg);
    cudaGetSymbolAddress((void**)&p_hnew_all, g_hnew_all);
    cudaGetSymbolAddress((void**)&p_Wenc_t,   g_Wenc_t);
    cudaGetSymbolAddress((void**)&p_Wihe_t,   g_Wihe_t);
    cudaGetSymbolAddress((void**)&p_Wout_t,   g_Wout_t);
    cudaGetSymbolAddress((void**)&p_feat_t,   g_feat_t);

    // 1: pack weights + tf32 pre-rounding + reset barrier tree
    prep_weights<<<(Vc * Hc + 255) / 256, 256>>>(
        W_dec, W_fbeta, W_hh, b_dec, b_fbeta, b_ih, b_hh,
        W_init_h, W_init_c, b_init_h, b_init_c,
        W_enc, W_ih, W_out);

    // 2: feature mean + embedding gather + features tf32 copy
    gather<<<2048 + (Bc * Lc * Fc) / 512, 512>>>(features, W_emb, captions);

    // 3: embedding gates (all steps)  [1984, 2048] = xemb @ Wihe^T
    gemm_tc<0><<<dim3(2048 / 64, TMAX), 256>>>(
        TMAX * Bc, 2048, Ec, (const unsigned*)p_xemb, p_Wihe_t, Ec, nullptr,
        p_embg, 2048, nullptr, nullptr);

    // 4: attention keys  [12544, 512] = feat_t @ Wenc_t^T + b_enc
    gemm_tc<0><<<dim3(Ac / 64, (Bc * Lc) / 64), 256>>>(
        Bc * Lc, Ac, Fc, p_feat_t, p_Wenc_t, Fc, b_enc,
        p_en_att, Ac, nullptr, nullptr);

    // 5: the entire recurrence (h0/c0 + 31 steps), persistent
    step_loop<<<NCTA, 256>>>(features, W_ih, W_full, lengths, alpha_out);

    // 6: batched vocab projection
    gemm_tc<2><<<dim3((Vc + 63) / 64, TMAX), 256>>>(
        TMAX * Bc, Vc, Hc, (const unsigned*)p_hnew_all, p_Wout_t, Hc, b_out,
        nullptr, 0, lengths, out);
}

// round 17
// speedup vs baseline: 1.0420x; 1.0420x over previous
#include <cuda_runtime.h>
#include <math.h>

// ---------------------------------------------------------------------------
// Problem constants
// ---------------------------------------------------------------------------
namespace {
constexpr int Bc = 64, Tc = 32, TMAX = 31;
constexpr int Fc = 512, Lc = 196, Ec = 512, Hc = 512, Ac = 512, Vc = 10000;
constexpr int NCAT = 3072;            // de(512) | fbeta(512) | hh gates(2048)
constexpr long long PRED_SZ = (long long)Bc * TMAX * Vc;   // 19,840,000
constexpr int NCTA = 296;             // persistent grid: 2 CTAs per SM
// tc GEMM v3 tile params
constexpr int TC_BM = 64, TC_BN = 128, TC_BK = 32, TC_PAD = 4, TC_STG = 3;
constexpr int TC_SMEM = TC_STG * (TC_BM + TC_BN) * (TC_BK + TC_PAD) * 4; // 82944
}

// ---------------------------------------------------------------------------
// Static scratch (no allocations allowed)
// ---------------------------------------------------------------------------
__device__ float g_en_att[Bc * Lc * Ac];          // [B*L, A]
__device__ float g_meanf[Bc * Fc];
__device__ float g_hc[Bc * 1024];                 // h = cols[0:512), c = cols[512:1024)
__device__ float g_hp[4 * Bc * NCAT];             // hproj partials (4 k-split planes)
__device__ float g_scp[2 * Bc * 200];             // partial attention scores (a-halves)
__device__ float g_xz[Bc * Fc];                   // gated context z
__device__ float g_Wcat[NCAT * Hc];               // [W_dec ; W_fbeta ; W_hh]
__device__ float g_bcat[NCAT];
__device__ float g_Winit[1024 * Fc];              // [W_init_h ; W_init_c]
__device__ float g_binit[1024];
__device__ float g_xemb[TMAX * Bc * Ec];          // gathered embeddings (tf32-rounded)
__device__ float g_embg[TMAX * Bc * 2048];        // emb @ W_ih_emb^T
__device__ float g_hnew_all[TMAX * Bc * Hc];      // unmasked h_new (tf32-rounded)
__device__ unsigned g_barrier;                    // monotonic grid barrier

// tf32-prerounded GEMM operands (bit patterns of rna-rounded fp32)
__device__ unsigned g_Wenc_t[Ac * Fc];            // W_enc
__device__ unsigned g_Wihe_t[2048 * Ec];          // W_ih[:, 0:512] dense
__device__ unsigned g_Wout_t[Vc * Hc];            // W_out
__device__ unsigned g_feat_t[Bc * Lc * Fc];       // features (as [B*L, F])

__device__ __forceinline__ float tanh_fast(float x) {
    float y;
    asm("tanh.approx.f32 %0, %1;" : "=f"(y) : "f"(x));
    return y;
}
__device__ __forceinline__ float sigmoid_fast(float x) {
    return 1.0f / (1.0f + __expf(-x));
}
__device__ __forceinline__ unsigned f2tf32(float x) {
    unsigned r;
    asm("cvt.rna.tf32.f32 %0, %1;" : "=r"(r) : "f"(x));
    return r;
}

// ---------------------------------------------------------------------------
// Launch 1: weight packing + tf32 pre-rounding + barrier reset
// ---------------------------------------------------------------------------
__global__ void prep_weights(const float* __restrict__ Wdec,
                             const float* __restrict__ Wfb,
                             const float* __restrict__ Whh,
                             const float* __restrict__ bdec,
                             const float* __restrict__ bfb,
                             const float* __restrict__ bih,
                             const float* __restrict__ bhh,
                             const float* __restrict__ Wih_,
                             const float* __restrict__ Wic_,
                             const float* __restrict__ bih0,
                             const float* __restrict__ bic0,
                             const float* __restrict__ Wenc,
                             const float* __restrict__ WihFull,
                             const float* __restrict__ Wout)
{
    int idx = blockIdx.x * 256 + threadIdx.x;
    if (idx == 0) g_barrier = 0u;
    if (idx < NCAT * Hc) {
        int n = idx / Hc, k = idx % Hc;
        float v;
        if (n < 512)       v = Wdec[n * Hc + k];
        else if (n < 1024) v = Wfb[(n - 512) * Hc + k];
        else               v = Whh[(n - 1024) * Hc + k];
        g_Wcat[idx] = v;
    }
    if (idx < NCAT) {
        float v;
        if (idx < 512)       v = bdec[idx];
        else if (idx < 1024) v = bfb[idx - 512];
        else                 v = bih[idx - 1024] + bhh[idx - 1024];
        g_bcat[idx] = v;
    }
    if (idx < 1024 * Fc) {
        int n = idx / Fc, k = idx % Fc;
        g_Winit[idx] = (n < 512) ? Wih_[n * Fc + k] : Wic_[(n - 512) * Fc + k];
    }
    if (idx < 1024)
        g_binit[idx] = (idx < 512) ? bih0[idx] : bic0[idx - 512];

    // tf32 pre-rounding
    if (idx < Ac * Fc)
        g_Wenc_t[idx] = f2tf32(Wenc[idx]);
    if (idx < 2048 * Ec) {
        int n = idx >> 9, k = idx & 511;
        g_Wihe_t[idx] = f2tf32(WihFull[(size_t)n * 1024 + k]);
    }
    if (idx < Vc * Hc)
        g_Wout_t[idx] = f2tf32(Wout[idx]);
}

// ---------------------------------------------------------------------------
// Launch 2: mean over L + embedding gather + features tf32 copy (merged)
// ---------------------------------------------------------------------------
__global__ void gather(const float* __restrict__ feat,
                       const float* __restrict__ Wemb,
                       const int* __restrict__ captions)
{
    if (blockIdx.x < 64) {
        int b = blockIdx.x, f = threadIdx.x;   // 512 threads
        const float* p = feat + (size_t)b * Fc * Lc + (size_t)f * Lc;
        float s = 0.f;
        #pragma unroll 4
        for (int l = 0; l < Lc; ++l) s += p[l];
        g_meanf[b * Fc + f] = s * (1.0f / (float)Lc);
    } else if (blockIdx.x < 2048) {
        int u = blockIdx.x - 64;
        int t = u >> 6, b = u & 63, e = threadIdx.x;
        int tok = captions[b * Tc + t];
        float w = Wemb[(size_t)tok * Ec + e];
        g_xemb[((size_t)t * Bc + b) * Ec + e] = __uint_as_float(f2tf32(w));
    } else {
        size_t i = (size_t)(blockIdx.x - 2048) * 512 + threadIdx.x;
        g_feat_t[i] = f2tf32(feat[i]);
    }
}

// ---------------------------------------------------------------------------
// Grid barrier (R14 best-known): release-red arrive + acquire-load poll
// ---------------------------------------------------------------------------
__device__ __forceinline__ void gsync(unsigned& epoch)
{
    __syncthreads();
    if (threadIdx.x == 0) {
        asm volatile("red.release.gpu.global.add.u32 [%0], %1;"
                     :: "l"(&g_barrier), "r"(1u) : "memory");
        epoch += NCTA;
        unsigned v;
        do {
            asm volatile("ld.acquire.gpu.global.u32 %0, [%1];"
                         : "=r"(v) : "l"(&g_barrier) : "memory");
        } while (v < epoch);
    }
    __syncthreads();
}

// ---------------------------------------------------------------------------
// 64x32 fp32 tile GEMM (double-buffered, BK=16, 256 threads, TM4 x TN2)
// ---------------------------------------------------------------------------
__device__ __forceinline__ void tile_gemm(
    const float* __restrict__ A, int ldA,
    const float* __restrict__ Brow, int ldB,
    int koff, int ktiles,
    const float* __restrict__ bias,
    float* __restrict__ dst, int ldC,
    float (&As)[2][16][64], float (&Bs)[2][16][32])
{
    const int tid = threadIdx.x;
    const int tx = tid & 15, ty = tid >> 4;
    const int arow = tid >> 2, acol = (tid & 3) * 4;
    const int brow = tid >> 3, bcol = (tid & 7) * 2;

    const float* aptr = A + (size_t)arow * ldA + koff + acol;
    const float* bptr = Brow + (size_t)brow * ldB + koff + bcol;

    float acc[4][2];
    #pragma unroll
    for (int i = 0; i < 4; ++i) { acc[i][0] = 0.f; acc[i][1] = 0.f; }

    float4 av = *reinterpret_cast<const float4*>(aptr);
    float2 bv = *reinterpret_cast<const float2*>(bptr);
    As[0][acol + 0][arow] = av.x; As[0][acol + 1][arow] = av.y;
    As[0][acol + 2][arow] = av.z; As[0][acol + 3][arow] = av.w;
    Bs[0][bcol + 0][brow] = bv.x; Bs[0][bcol + 1][brow] = bv.y;
    __syncthreads();

    for (int it = 0; it < ktiles; ++it) {
        const int cur = it & 1;
        if (it + 1 < ktiles) {
            av = *reinterpret_cast<const float4*>(aptr + (it + 1) * 16);
            bv = *reinterpret_cast<const float2*>(bptr + (it + 1) * 16);
        }
        #pragma unroll
        for (int k = 0; k < 16; ++k) {
            float4 a4 = *reinterpret_cast<const float4*>(&As[cur][k][ty * 4]);
            float2 b2 = *reinterpret_cast<const float2*>(&Bs[cur][k][tx * 2]);
            acc[0][0] += a4.x * b2.x; acc[0][1] += a4.x * b2.y;
            acc[1][0] += a4.y * b2.x; acc[1][1] += a4.y * b2.y;
            acc[2][0] += a4.z * b2.x; acc[2][1] += a4.z * b2.y;
            acc[3][0] += a4.w * b2.x; acc[3][1] += a4.w * b2.y;
        }
        if (it + 1 < ktiles) {
            const int nxt = cur ^ 1;
            As[nxt][acol + 0][arow] = av.x; As[nxt][acol + 1][arow] = av.y;
            As[nxt][acol + 2][arow] = av.z; As[nxt][acol + 3][arow] = av.w;
            Bs[nxt][bcol + 0][brow] = bv.x; Bs[nxt][bcol + 1][brow] = bv.y;
        }
        __syncthreads();
    }

    #pragma unroll
    for (int i = 0; i < 4; ++i) {
        float b0 = bias ? bias[tx * 2 + 0] : 0.f;
        float b1 = bias ? bias[tx * 2 + 1] : 0.f;
        float* d = dst + (size_t)(ty * 4 + i) * ldC + tx * 2;
        d[0] = acc[i][0] + b0;
        d[1] = acc[i][1] + b1;
    }
}

// ---------------------------------------------------------------------------
// Persistent step loop (phase structure = R12/R14 best known)
// ---------------------------------------------------------------------------
__global__ __launch_bounds__(256, 2) void step_loop(
    const float* __restrict__ features,
    const float* __restrict__ W_ih,
    const float* __restrict__ Wfull,
    const int*   __restrict__ lengths,
    float* __restrict__ alpha_out)
{
    __shared__ float As[2][16][64];
    __shared__ float Bs[2][16][32];
    __shared__ float A4[2][16][17];
    __shared__ float B4[2][16][68];
    __shared__ float sg[16][68];
    __shared__ float s_de[256];
    __shared__ float s_wf[256];
    __shared__ float s_sc[200];
    __shared__ float s_red[256];

    const int bid = blockIdx.x;
    const int tid = threadIdx.x;
    unsigned epoch = 0;

    // ---- P0: h0/c0 = meanf @ Winit^T + binit (32 units, full K) -----------
    if (bid < 32) {
        const int n0 = bid * 32;
        tile_gemm(g_meanf, 512, g_Winit + (size_t)n0 * 512, 512, 0, 32,
                  g_binit + n0, g_hc + n0, 1024, As, Bs);
    }
    gsync(epoch);

    for (int t = 0; t < TMAX; ++t) {
        // ---- P1: de/fbeta partials: 32 tiles(32col) x split-4 -------------
        if (bid < 128) {
            const int s = bid >> 5, n0 = (bid & 31) * 32;
            tile_gemm(g_hc, 1024, g_Wcat + (size_t)n0 * 512, 512,
                      s * 128, 8, nullptr,
                      g_hp + (size_t)s * Bc * NCAT + n0, NCAT, As, Bs);
        }
        gsync(epoch);

        // ---- P2: partial scores (a-halves) || hh units 0..127 -------------
        if (bid >= 128 && bid < 256) {
            const int u = bid - 128;
            const int b = u & 63, ah = u >> 6;
            if ((lengths[b] - 1) > t) {
                {
                    const int a = ah * 256 + tid;
                    float d = g_bcat[a];
                    #pragma unroll
                    for (int s = 0; s < 4; ++s)
                        d += g_hp[((size_t)s * Bc + b) * NCAT + a];
                    s_de[tid] = d;
                    s_wf[tid] = Wfull[a];
                }
                __syncthreads();
                const int warp = tid >> 5, lane = tid & 31;
                for (int l = warp; l < Lc; l += 8) {
                    const float* ea = g_en_att + ((size_t)b * Lc + l) * Ac
                                               + ah * 256;
                    float s = 0.f;
                    #pragma unroll
                    for (int i = lane; i < 256; i += 32)
                        s += tanh_fast(ea[i] + s_de[i]) * s_wf[i];
                    #pragma unroll
                    for (int o = 16; o > 0; o >>= 1)
                        s += __shfl_xor_sync(0xffffffffu, s, o);
                    if (lane == 0)
                        g_scp[((size_t)ah * Bc + b) * 200 + l] = s;
                }
            }
        } else if (bid < 128) {
            const int s = bid >> 6, n0 = 1024 + (bid & 63) * 32;
            tile_gemm(g_hc, 1024, g_Wcat + (size_t)n0 * 512, 512,
                      s * 128, 8, nullptr,
                      g_hp + (size_t)s * Bc * NCAT + n0, NCAT, As, Bs);
        }
        gsync(epoch);

        // ---- P3: softmax + z (f-halves) || hh units 128..255 --------------
        if (bid >= 128 && bid < 256) {
            const int u = bid - 128;
            const int b = u & 63, fh = u >> 6;
            const bool active = (lengths[b] - 1) > t;
            if (!active) {
                if (fh == 0 && tid < Lc)
                    alpha_out[((size_t)b * TMAX + t) * Lc + tid] = 0.f;
            } else {
                float v = (tid < Lc)
                    ? g_scp[(size_t)b * 200 + tid] +
                      g_scp[((size_t)Bc + b) * 200 + tid]
                    : -3.4e38f;
                s_red[tid] = v; __syncthreads();
                for (int s = 128; s > 0; s >>= 1) {
                    if (tid < s) s_red[tid] = fmaxf(s_red[tid], s_red[tid + s]);
                    __syncthreads();
                }
                float mx = s_red[0]; __syncthreads();
                float e = (tid < Lc) ? __expf(v - mx) : 0.f;
                s_red[tid] = e; __syncthreads();
                for (int s = 128; s > 0; s >>= 1) {
                    if (tid < s) s_red[tid] += s_red[tid + s];
                    __syncthreads();
                }
                float inv = 1.f / s_red[0];
                if (tid < Lc) {
                    float a = e * inv;
                    s_sc[tid] = a;
                    if (fh == 0)
                        alpha_out[((size_t)b * TMAX + t) * Lc + tid] = a;
                }
                __syncthreads();

                const int f = fh * 256 + tid;
                float fb = g_bcat[512 + f];
                #pragma unroll
                for (int s = 0; s < 4; ++s)
                    fb += g_hp[((size_t)s * Bc + b) * NCAT + 512 + f];
                const float* fp = features + (size_t)b * Lc * Fc + f;
                float acc = 0.f;
                #pragma unroll 4
                for (int l = 0; l < Lc; ++l)
                    acc += fp[(size_t)l * Fc] * s_sc[l];
                g_xz[b * Fc + f] = acc * sigmoid_fast(fb);
            }
        } else if (bid < 128) {
            const int s = 2 + (bid >> 6), n0 = 1024 + (bid & 63) * 32;
            tile_gemm(g_hc, 1024, g_Wcat + (size_t)n0 * 512, 512,
                      s * 128, 8, nullptr,
                      g_hp + (size_t)s * Bc * NCAT + n0, NCAT, As, Bs);
        }
        gsync(epoch);

        // ---- P4: gate-grouped z-GEMM (16x64 tile, full K) + fused LSTM ----
        if (bid < 128) {
            const int bt = bid >> 5, ng = bid & 31;
            const int b0 = bt * 16;
            const int tx = tid & 15, ty = tid >> 4;

            const int ar = tid >> 2, ac = (tid & 3) * 4;
            const float* aptr = g_xz + (size_t)(b0 + (ar & 15)) * 512 + ac;
            const int br = tid >> 2, bc = (tid & 3) * 4;
            const int grow = (br >> 4) * 512 + ng * 16 + (br & 15);
            const float* bptr = W_ih + (size_t)grow * 1024 + 512 + bc;

            float acc0 = 0.f, acc1 = 0.f, acc2 = 0.f, acc3 = 0.f;
            float4 av, bv;
            if (tid < 64) av = *reinterpret_cast<const float4*>(aptr);
            bv = *reinterpret_cast<const float4*>(bptr);
            if (tid < 64) {
                A4[0][ac + 0][ar] = av.x; A4[0][ac + 1][ar] = av.y;
                A4[0][ac + 2][ar] = av.z; A4[0][ac + 3][ar] = av.w;
            }
            B4[0][bc + 0][br] = bv.x; B4[0][bc + 1][br] = bv.y;
            B4[0][bc + 2][br] = bv.z; B4[0][bc + 3][br] = bv.w;
            __syncthreads();

            for (int it2 = 0; it2 < 32; ++it2) {
                const int cur = it2 & 1;
                if (it2 + 1 < 32) {
                    if (tid < 64)
                        av = *reinterpret_cast<const float4*>(aptr + (it2 + 1) * 16);
                    bv = *reinterpret_cast<const float4*>(bptr + (it2 + 1) * 16);
                }
                #pragma unroll
                for (int k = 0; k < 16; ++k) {
                    float a = A4[cur][k][ty];
                    float4 b4 = *reinterpret_cast<const float4*>(&B4[cur][k][tx * 4]);
                    acc0 += a * b4.x; acc1 += a * b4.y;
                    acc2 += a * b4.z; acc3 += a * b4.w;
                }
                if (it2 + 1 < 32) {
                    const int nxt = cur ^ 1;
                    if (tid < 64) {
                        A4[nxt][ac + 0][ar] = av.x; A4[nxt][ac + 1][ar] = av.y;
                        A4[nxt][ac + 2][ar] = av.z; A4[nxt][ac + 3][ar] = av.w;
                    }
                    B4[nxt][bc + 0][br] = bv.x; B4[nxt][bc + 1][br] = bv.y;
                    B4[nxt][bc + 2][br] = bv.z; B4[nxt][bc + 3][br] = bv.w;
                }
                __syncthreads();
            }

            sg[ty][tx * 4 + 0] = acc0; sg[ty][tx * 4 + 1] = acc1;
            sg[ty][tx * 4 + 2] = acc2; sg[ty][tx * 4 + 3] = acc3;
            __syncthreads();

            {
                const int bl = tid >> 4, nl = tid & 15;
                const int b = b0 + bl, n = ng * 16 + nl;
                const bool active = (lengths[b] - 1) > t;
                float gate[4];
                #pragma unroll
                for (int g = 0; g < 4; ++g) {
                    const int col = g * 512 + n;
                    float v = sg[bl][g * 16 + nl]
                            + g_bcat[1024 + col]
                            + g_embg[((size_t)t * Bc + b) * 2048 + col];
                    #pragma unroll
                    for (int s = 0; s < 4; ++s)
                        v += g_hp[((size_t)s * Bc + b) * NCAT + 1024 + col];
                    gate[g] = v;
                }
                float c  = g_hc[b * 1024 + 512 + n];
                float si = sigmoid_fast(gate[0]);
                float sf = sigmoid_fast(gate[1]);
                float so = sigmoid_fast(gate[3]);
                float cn = sf * c + si * tanhf(gate[2]);
                float hn = so * tanhf(cn);
                g_hnew_all[((size_t)t * Bc + b) * Hc + n] =
                    __uint_as_float(f2tf32(hn));
                if (active) {
                    g_hc[b * 1024 + n]       = hn;
                    g_hc[b * 1024 + 512 + n] = cn;
                }
            }
        }
        gsync(epoch);
    }
}

// ---------------------------------------------------------------------------
// tf32 tensor-core NT GEMM v3: BM64 x BN128, 3-stage cp.async ring,
// one __syncthreads per k-iter, operands pre-rounded. Dynamic smem.
//   MODE 0: normal store; MODE 2: vocab scatter, inactive rows zeroed.
// ---------------------------------------------------------------------------
template<int MODE>
__global__ __launch_bounds__(256) void gemm_tc(
    int M, int N, int K,
    const unsigned* __restrict__ A,
    const unsigned* __restrict__ B, int ldB,
    const float* __restrict__ bias,
    float* __restrict__ C, int ldC,
    const int* __restrict__ lengths, float* __restrict__ predBase)
{
    constexpr int BM = TC_BM, BN = TC_BN, BK = TC_BK, PAD = TC_PAD;
    constexpr int LDS_ROW = BK + PAD;                 // 36
    extern __shared__ unsigned smem_tc[];
    unsigned* Asb = smem_tc;                          // [3][64][36]
    unsigned* Bsb = smem_tc + TC_STG * BM * LDS_ROW;  // [3][128][36]

    const int tid = threadIdx.x;
    const int lane = tid & 31, wid = tid >> 5;
    const int wm = wid & 3, wn = wid >> 2;            // warp tile 16m x 64n
    const int g = lane >> 2, tg = lane & 3;
    const int bm = blockIdx.y * BM, bn = blockIdx.x * BN;

    // A loader: row tid>>2 (0..63), 8 uints at col (tid&3)*8
    const int alr = tid >> 2, alc = (tid & 3) * 8;
    const unsigned* ap = A + (size_t)(bm + alr) * K + alc;
    // B loader: row tid>>1 (0..127), 16 uints at col (tid&1)*16
    const int blr = tid >> 1, blc = (tid & 1) * 16;
    const bool bval = (bn + blr) < N;
    const unsigned* bp = B + (bval ? (size_t)(bn + blr) * ldB : 0) + blc;
    const int bsz = bval ? 16 : 0;

    const unsigned sa0 = (unsigned)__cvta_generic_to_shared(Asb)
                       + (unsigned)(alr * LDS_ROW + alc) * 4u;
    const unsigned sb0 = (unsigned)__cvta_generic_to_shared(Bsb)
                       + (unsigned)(blr * LDS_ROW + blc) * 4u;
    const unsigned abuf = (unsigned)(BM * LDS_ROW * 4);
    const unsigned bbuf = (unsigned)(BN * LDS_ROW * 4);

    float acc[8][4];
    #pragma unroll
    for (int i = 0; i < 8; ++i)
        #pragma unroll
        for (int j = 0; j < 4; ++j) acc[i][j] = 0.f;

    auto stage = [&](int buf, int it) {
        const unsigned* a = ap + it * BK;
        const unsigned* b = bp + it * BK;
        unsigned da = sa0 + buf * abuf;
        unsigned db = sb0 + buf * bbuf;
        asm volatile("cp.async.ca.shared.global [%0], [%1], 16;"
                     :: "r"(da), "l"(a));
        asm volatile("cp.async.ca.shared.global [%0], [%1], 16;"
                     :: "r"(da + 16), "l"(a + 4));
        asm volatile("cp.async.ca.shared.global [%0], [%1], 16, %2;"
                     :: "r"(db), "l"(b), "r"(bsz));
        asm volatile("cp.async.ca.shared.global [%0], [%1], 16, %2;"
                     :: "r"(db + 16), "l"(b + 4), "r"(bsz));
        asm volatile("cp.async.ca.shared.global [%0], [%1], 16, %2;"
                     :: "r"(db + 32), "l"(b + 8), "r"(bsz));
        asm volatile("cp.async.ca.shared.global [%0], [%1], 16, %2;"
                     :: "r"(db + 48), "l"(b + 12), "r"(bsz));
        asm volatile("cp.async.commit_group;");
    };

    const int nt = K / BK;
    stage(0, 0);
    if (nt > 1) stage(1, 1);

    int cur = 0;
    for (int it = 0; it < nt; ++it) {
        if (it + 1 < nt)
            asm volatile("cp.async.wait_group 1;");
        else
            asm volatile("cp.async.wait_group 0;");
        __syncthreads();
        if (it + 2 < nt) stage((cur + 2) % TC_STG, it + 2);

        const unsigned* Ab = Asb + cur * BM * LDS_ROW;
        const unsigned* Bb = Bsb + cur * BN * LDS_ROW;

        #pragma unroll
        for (int ks = 0; ks < 4; ++ks) {
            const int k0 = ks * 8;
            unsigned fa0 = Ab[(wm * 16 + g) * LDS_ROW + k0 + tg];
            unsigned fa1 = Ab[(wm * 16 + g + 8) * LDS_ROW + k0 + tg];
            unsigned fa2 = Ab[(wm * 16 + g) * LDS_ROW + k0 + tg + 4];
            unsigned fa3 = Ab[(wm * 16 + g + 8) * LDS_ROW + k0 + tg + 4];
            #pragma unroll
            for (int t8 = 0; t8 < 8; ++t8) {
                unsigned fb0 = Bb[(wn * 64 + t8 * 8 + g) * LDS_ROW + k0 + tg];
                unsigned fb1 = Bb[(wn * 64 + t8 * 8 + g) * LDS_ROW + k0 + tg + 4];
                asm volatile(
                    "mma.sync.aligned.m16n8k8.row.col.f32.tf32.tf32.f32 "
                    "{%0,%1,%2,%3}, {%4,%5,%6,%7}, {%8,%9}, {%0,%1,%2,%3};"
                    : "+f"(acc[t8][0]), "+f"(acc[t8][1]),
                      "+f"(acc[t8][2]), "+f"(acc[t8][3])
                    : "r"(fa0), "r"(fa1), "r"(fa2), "r"(fa3),
                      "r"(fb0), "r"(fb1));
            }
        }
        cur = (cur + 1) % TC_STG;
    }

    #pragma unroll
    for (int t8 = 0; t8 < 8; ++t8) {
        const int col = bn + wn * 64 + t8 * 8 + 2 * tg;
        if (col >= N) continue;
        float bb0 = bias ? bias[col]     : 0.f;
        float bb1 = bias ? bias[col + 1] : 0.f;
        #pragma unroll
        for (int half = 0; half < 2; ++half) {
            const int m = bm + wm * 16 + g + half * 8;
            float v0 = acc[t8][half * 2 + 0] + bb0;
            float v1 = acc[t8][half * 2 + 1] + bb1;
            float* dst;
            if (MODE == 2) {
                const int b = m & 63, t = m >> 6;
                if (!((lengths[b] - 1) > t)) { v0 = 0.f; v1 = 0.f; }
                dst = predBase + ((size_t)b * TMAX + t) * Vc + col;
            } else {
                dst = C + (size_t)m * ldC + col;
            }
            *reinterpret_cast<float2*>(dst) = make_float2(v0, v1);
        }
    }
}

// ---------------------------------------------------------------------------
// Host driver: 6 launches total (graph-capturable)
// ---------------------------------------------------------------------------
extern "C" void kernel_launch(void* const* d_in, const int* in_sizes, int n_in,
                              void* d_out, int out_size)
{
    const float* features = (const float*)d_in[0];
    const int*   captions = (const int*)  d_in[1];
    const int*   lengths  = (const int*)  d_in[2];
    const float* W_emb    = (const float*)d_in[3];
    const float* W_enc    = (const float*)d_in[4];
    const float* b_enc    = (const float*)d_in[5];
    const float* W_dec    = (const float*)d_in[6];
    const float* b_dec    = (const float*)d_in[7];
    const float* W_full   = (const float*)d_in[8];
    /* d_in[9] = b_full: softmax shift-invariant, unused */
    const float* W_fbeta  = (const float*)d_in[10];
    const float* b_fbeta  = (const float*)d_in[11];
    const float* W_ih     = (const float*)d_in[12];
    const float* W_hh     = (const float*)d_in[13];
    const float* b_ih     = (const float*)d_in[14];
    const float* b_hh     = (const float*)d_in[15];
    const float* W_out    = (const float*)d_in[16];
    const float* b_out    = (const float*)d_in[17];
    const float* W_init_h = (const float*)d_in[18];
    const float* b_init_h = (const float*)d_in[19];
    const float* W_init_c = (const float*)d_in[20];
    const float* b_init_c = (const float*)d_in[21];

    float* out       = (float*)d_out;
    float* alpha_out = out + PRED_SZ;

    float *p_en_att, *p_xemb, *p_embg, *p_hnew_all;
    unsigned *p_Wenc_t, *p_Wihe_t, *p_Wout_t, *p_feat_t;
    cudaGetSymbolAddress((void**)&p_en_att,   g_en_att);
    cudaGetSymbolAddress((void**)&p_xemb,     g_xemb);
    cudaGetSymbolAddress((void**)&p_embg,     g_embg);
    cudaGetSymbolAddress((void**)&p_hnew_all, g_hnew_all);
    cudaGetSymbolAddress((void**)&p_Wenc_t,   g_Wenc_t);
    cudaGetSymbolAddress((void**)&p_Wihe_t,   g_Wihe_t);
    cudaGetSymbolAddress((void**)&p_Wout_t,   g_Wout_t);
    cudaGetSymbolAddress((void**)&p_feat_t,   g_feat_t);

    // raise dynamic smem limit for gemm_tc instantiations (idempotent)
    cudaFuncSetAttribute(gemm_tc<0>,
        cudaFuncAttributeMaxDynamicSharedMemorySize, TC_SMEM);
    cudaFuncSetAttribute(gemm_tc<2>,
        cudaFuncAttributeMaxDynamicSharedMemorySize, TC_SMEM);

    // 1: pack weights + tf32 pre-rounding + reset barrier
    prep_weights<<<(Vc * Hc + 255) / 256, 256>>>(
        W_dec, W_fbeta, W_hh, b_dec, b_fbeta, b_ih, b_hh,
        W_init_h, W_init_c, b_init_h, b_init_c,
        W_enc, W_ih, W_out);

    // 2: feature mean + embedding gather + features tf32 copy
    gather<<<2048 + (Bc * Lc * Fc) / 512, 512>>>(features, W_emb, captions);

    // 3: embedding gates (all steps)  [1984, 2048] = xemb @ Wihe^T
    gemm_tc<0><<<dim3(2048 / 128, TMAX), 256, TC_SMEM>>>(
        TMAX * Bc, 2048, Ec, (const unsigned*)p_xemb, p_Wihe_t, Ec, nullptr,
        p_embg, 2048, nullptr, nullptr);

    // 4: attention keys  [12544, 512] = feat_t @ Wenc_t^T + b_enc
    gemm_tc<0><<<dim3(Ac / 128, (Bc * Lc) / 64), 256, TC_SMEM>>>(
        Bc * Lc, Ac, Fc, p_feat_t, p_Wenc_t, Fc, b_enc,
        p_en_att, Ac, nullptr, nullptr);

    // 5: the entire recurrence (h0/c0 + 31 steps), persistent
    step_loop<<<NCTA, 256>>>(features, W_ih, W_full, lengths, alpha_out);

    // 6: batched vocab projection
    gemm_tc<2><<<dim3((Vc + 127) / 128, TMAX), 256, TC_SMEM>>>(
        TMAX * Bc, Vc, Hc, (const unsigned*)p_hnew_all, p_Wout_t, Hc, b_out,
        nullptr, 0, lengths, out);
}